// round 13
// baseline (speedup 1.0000x reference)
#include <cuda_runtime.h>
#include <cuda_fp16.h>
#include <stdint.h>
#include <math.h>

constexpr int I_SZ = 256, D_SZ = 128, HD = 32768, MB = 64;
constexpr int ROWB = 272;                    // padded row: 136 halfs = 272 B
constexpr uint32_t A_PLANE = 64 * ROWB;      // 17408 B  [64][136] fp16
constexpr uint32_t U_PLANE = 128 * ROWB;     // 34816 B  [128][136] fp16
constexpr uint32_t SM_A  = 0;                // fp16 A plane (hg, later rh)
constexpr uint32_t SM_U  = A_PLANE;          // single U buffer (Uz -> Ur -> Uh)
constexpr uint32_t SM_WB = SM_U + U_PLANE;   // 52224; 6*128 floats
constexpr uint32_t SM_X  = SM_WB + 3072;     // 64 floats
constexpr uint32_t SMEM_MAIN = SM_X + 256;   // 55552 B -> 4 CTAs/SM (222 KB)

// U scratch: [gate z/r/h][group] -> 32KB fp16 [n=128][k=128]
__device__ __align__(256) unsigned char g_Uscr[3ull * 256 * 32768];

__device__ __forceinline__ uint32_t smem_u32(const void* p) {
    uint32_t a;
    asm("{ .reg .u64 t; cvta.to.shared.u64 t, %1; cvt.u32.u64 %0, t; }" : "=r"(a) : "l"(p));
    return a;
}
#define CP16(dst, src) asm volatile("cp.async.cg.shared.global [%0], [%1], 16;" :: "r"(dst), "l"(src))
#define CP_COMMIT()    asm volatile("cp.async.commit_group;" ::: "memory")
#define CP_WAIT(n)     asm volatile("cp.async.wait_group %0;" :: "n"(n) : "memory")
#define LDSM4(R, addr)                                                          \
    asm volatile("ldmatrix.sync.aligned.m8n8.x4.shared.b16 {%0,%1,%2,%3}, [%4];"\
        : "=r"((R)[0]), "=r"((R)[1]), "=r"((R)[2]), "=r"((R)[3]) : "r"(addr))
#define MMA16816(c, a0, a1, a2, a3, b0, b1)                                     \
    asm volatile("mma.sync.aligned.m16n8k16.row.col.f32.f16.f16.f32 "           \
        "{%0,%1,%2,%3}, {%4,%5,%6,%7}, {%8,%9}, {%0,%1,%2,%3};"                 \
        : "+f"((c)[0]), "+f"((c)[1]), "+f"((c)[2]), "+f"((c)[3])                \
        : "r"(a0), "r"(a1), "r"(a2), "r"(a3), "r"(b0), "r"(b1))

// HW tanh (MUFU.TANH, sm_75+): 1 MUFU vs 2 for the __expf path
__device__ __forceinline__ float tanha(float x) {
    float y;
    asm("tanh.approx.f32 %0, %1;" : "=f"(y) : "f"(x));
    return y;
}
__device__ __forceinline__ float sigf(float x) {      // sigmoid = 0.5 + 0.5*tanh(x/2)
    return fmaf(tanha(0.5f * x), 0.5f, 0.5f);
}

// ---------- prep: U[i][k][n] -> B[n][k] fp16 plane ----------
__global__ __launch_bounds__(256) void gru_prep(const float* __restrict__ Uz,
                                                const float* __restrict__ Ur,
                                                const float* __restrict__ Uh) {
    extern __shared__ float sf[];  // [128][129]
    const int i = blockIdx.x, g = blockIdx.y, tid = threadIdx.x;
    const float* Ui = ((g == 0) ? Uz : (g == 1) ? Ur : Uh) + (size_t)i * D_SZ * D_SZ;
    for (int t = tid; t < D_SZ * D_SZ; t += 256) sf[(t >> 7) * 129 + (t & 127)] = Ui[t];
    __syncthreads();
    unsigned char* hp = g_Uscr + (size_t)(g * 256 + i) * 32768;
    for (int c = tid; c < 2048; c += 256) {
        int n = c >> 4, k0 = (c & 15) * 8;
        uint32_t hw[4];
#pragma unroll
        for (int j = 0; j < 4; j++) {
            __half h0 = __float2half_rn(sf[(k0 + 2 * j) * 129 + n]);      // B[n][k]=U[k][n]
            __half h1 = __float2half_rn(sf[(k0 + 2 * j + 1) * 129 + n]);
            hw[j] = (uint32_t)__half_as_ushort(h0) | ((uint32_t)__half_as_ushort(h1) << 16);
        }
        *(uint4*)(hp + n * 256 + k0 * 2) = make_uint4(hw[0], hw[1], hw[2], hw[3]);
    }
}

// cp.async one U gate (32KB) into the smem U buffer
__device__ __forceinline__ void cp_u(uint32_t dst, const unsigned char* src, int tid) {
#pragma unroll
    for (int t = tid; t < 2048; t += 256) {
        uint32_t row = t >> 4, c = t & 15;
        CP16(dst + row * ROWB + c * 16, src + (size_t)t * 16);
    }
    CP_COMMIT();
}

// GEMM: acc += A * U   (warp tile M=32, N=32, K=128; 64 MMAs)
__device__ __forceinline__ void gemm1(uint32_t sb, int warp_m, int warp_n,
                                      uint32_t offA, uint32_t offB, float acc[2][4][4]) {
#pragma unroll
    for (int mi = 0; mi < 2; mi++)
#pragma unroll
        for (int ni = 0; ni < 4; ni++)
#pragma unroll
            for (int q = 0; q < 4; q++) acc[mi][ni][q] = 0.0f;
#pragma unroll
    for (int ks = 0; ks < 8; ks++) {
        const uint32_t kb = ks * 32;
        uint32_t A[2][4], B[2][4];
#pragma unroll
        for (int mi = 0; mi < 2; mi++)
            LDSM4(A[mi], sb + SM_A + (warp_m + mi * 16) * ROWB + kb + offA);
#pragma unroll
        for (int nj = 0; nj < 2; nj++)
            LDSM4(B[nj], sb + SM_U + (warp_n + nj * 16) * ROWB + kb + offB);
#pragma unroll
        for (int mi = 0; mi < 2; mi++)
#pragma unroll
            for (int nj = 0; nj < 2; nj++)
#pragma unroll
                for (int hh = 0; hh < 2; hh++)
                    MMA16816(acc[mi][nj * 2 + hh],
                             A[mi][0], A[mi][1], A[mi][2], A[mi][3],
                             B[nj][hh * 2], B[nj][hh * 2 + 1]);
    }
}

// ---------- main: M=64/CTA, single U buffer, 4 CTAs/SM ----------
__global__ __launch_bounds__(256, 4) void gru_main(
    const float* __restrict__ X, const float* __restrict__ hs,
    const float* __restrict__ Wr, const float* __restrict__ Wz, const float* __restrict__ Wh,
    const float* __restrict__ br, const float* __restrict__ bz, const float* __restrict__ bh,
    float* __restrict__ out_hnew, float* __restrict__ out_ht) {
    extern __shared__ __align__(16) unsigned char smem[];
    const uint32_t sb = smem_u32(smem);
    const int tid = threadIdx.x, warp = tid >> 5, l = tid & 31;
    const int i = blockIdx.y, b0 = blockIdx.x * MB;

    float* wb  = (float*)(smem + SM_WB);  // wz|bz|wr|br|wh|bh
    float* x_s = (float*)(smem + SM_X);

    const unsigned char* uz = g_Uscr + (size_t)(0 * 256 + i) * 32768;
    const unsigned char* ur = g_Uscr + (size_t)(1 * 256 + i) * 32768;
    const unsigned char* uh = g_Uscr + (size_t)(2 * 256 + i) * 32768;
    cp_u(sb + SM_U, uz, tid);

    if (tid < 128) {
        wb[tid]       = Wz[i * D_SZ + tid];
        wb[128 + tid] = bz[i * D_SZ + tid];
        wb[256 + tid] = Wr[i * D_SZ + tid];
        wb[384 + tid] = br[i * D_SZ + tid];
        wb[512 + tid] = Wh[i * D_SZ + tid];
        wb[640 + tid] = bh[i * D_SZ + tid];
    }
    if (tid < MB) x_s[tid] = X[(size_t)(b0 + tid) * I_SZ + i];

    // A <= fp16(hg)
    for (int c = tid; c < 1024; c += 256) {
        int row = c >> 4, k0 = (c & 15) * 8;
        const float4* g = (const float4*)(hs + (size_t)(b0 + row) * HD + (size_t)i * D_SZ + k0);
        float4 v0 = g[0], v1 = g[1];
        float v[8] = {v0.x, v0.y, v0.z, v0.w, v1.x, v1.y, v1.z, v1.w};
        uint32_t hw[4];
#pragma unroll
        for (int j = 0; j < 4; j++) {
            __half h0 = __float2half_rn(v[2 * j]), h1 = __float2half_rn(v[2 * j + 1]);
            hw[j] = (uint32_t)__half_as_ushort(h0) | ((uint32_t)__half_as_ushort(h1) << 16);
        }
        *(uint4*)(smem + SM_A + row * ROWB + k0 * 2) = make_uint4(hw[0], hw[1], hw[2], hw[3]);
    }
    CP_WAIT(0);
    __syncthreads();             // [1] A + Uz resident

    const int warp_m = (warp & 1) * 32, warp_n = (warp >> 1) * 32;
    const uint32_t offA = (uint32_t)((l & 15) * ROWB + (l >> 4) * 16);
    const uint32_t offB = (uint32_t)((l & 7) * ROWB + ((l >> 4) & 1) * (8 * ROWB) +
                                     ((l >> 3) & 1) * 16);
    float acc[2][4][4];
    half2 z2[2][4][2];           // z gate packed fp16 (8 regs)

    // ---- z gate ----
    gemm1(sb, warp_m, warp_n, offA, offB, acc);
    __syncthreads();             // [2] Uz reads done
    cp_u(sb + SM_U, ur, tid);    // Ur -> U, overlaps z epilogue
#pragma unroll
    for (int mi = 0; mi < 2; mi++)
#pragma unroll
        for (int j = 0; j < 4; j++) {
            int col = warp_n + j * 8 + (l & 3) * 2;
            float w0 = wb[col], w1 = wb[col + 1], c0 = wb[128 + col], c1 = wb[129 + col];
#pragma unroll
            for (int rr = 0; rr < 2; rr++) {
                int row = warp_m + mi * 16 + rr * 8 + (l >> 2);
                float xv = x_s[row];
                float z0 = sigf(acc[mi][j][rr * 2] + xv * w0 + c0);
                float z1 = sigf(acc[mi][j][rr * 2 + 1] + xv * w1 + c1);
                z2[mi][j][rr] = __floats2half2_rn(z0, z1);
            }
        }
    CP_WAIT(0);
    __syncthreads();             // [3] Ur resident

    // ---- r gate ----
    gemm1(sb, warp_m, warp_n, offA, offB, acc);
    __syncthreads();             // [4] Ur + A reads done
    cp_u(sb + SM_U, uh, tid);    // Uh -> U, overlaps r epilogue
#pragma unroll
    for (int mi = 0; mi < 2; mi++)
#pragma unroll
        for (int j = 0; j < 4; j++) {
            int col = warp_n + j * 8 + (l & 3) * 2;
            float w0 = wb[256 + col], w1 = wb[257 + col];
            float c0 = wb[384 + col], c1 = wb[385 + col];
#pragma unroll
            for (int rr = 0; rr < 2; rr++) {
                int row = warp_m + mi * 16 + rr * 8 + (l >> 2);
                float xv = x_s[row];
                half2* pA = (half2*)(smem + SM_A + row * ROWB + col * 2);
                half2 hg2 = *pA;
                float r0 = sigf(acc[mi][j][rr * 2] + xv * w0 + c0);
                float r1 = sigf(acc[mi][j][rr * 2 + 1] + xv * w1 + c1);
                *pA = __halves2half2(
                    __float2half_rn(r0 * __half2float(__low2half(hg2))),
                    __float2half_rn(r1 * __half2float(__high2half(hg2))));
            }
        }
    CP_WAIT(0);
    __syncthreads();             // [5] Uh + rh plane ready

    // ---- h gate + fused combine (tail: global hg via __ldg, no barrier) ----
    gemm1(sb, warp_m, warp_n, offA, offB, acc);
#pragma unroll
    for (int mi = 0; mi < 2; mi++)
#pragma unroll
        for (int j = 0; j < 4; j++) {
            int col = warp_n + j * 8 + (l & 3) * 2;
            float w0 = wb[512 + col], w1 = wb[513 + col];
            float c0 = wb[640 + col], c1 = wb[641 + col];
#pragma unroll
            for (int rr = 0; rr < 2; rr++) {
                int row = warp_m + mi * 16 + rr * 8 + (l >> 2);
                float xv = x_s[row];
                size_t gidx = (size_t)(b0 + row) * HD + (size_t)i * D_SZ + col;
                float2 hg = __ldg((const float2*)(hs + gidx));
                float t0 = tanha(acc[mi][j][rr * 2] + xv * w0 + c0);
                float t1 = tanha(acc[mi][j][rr * 2 + 1] + xv * w1 + c1);
                float z0 = __half2float(__low2half(z2[mi][j][rr]));
                float z1 = __half2float(__high2half(z2[mi][j][rr]));
                *(float2*)(out_ht + gidx)   = make_float2(t0, t1);
                *(float2*)(out_hnew + gidx) = make_float2(z0 * hg.x + (1.0f - z0) * t0,
                                                          z1 * hg.y + (1.0f - z1) * t1);
            }
        }
}

extern "C" void kernel_launch(void* const* d_in, const int* in_sizes, int n_in,
                              void* d_out, int out_size) {
    const float* X  = (const float*)d_in[0];
    const float* h  = (const float*)d_in[1];
    const float* Wr = (const float*)d_in[2];
    const float* Wz = (const float*)d_in[3];
    const float* Wh = (const float*)d_in[4];
    const float* Ur = (const float*)d_in[5];
    const float* Uz = (const float*)d_in[6];
    const float* Uh = (const float*)d_in[7];
    const float* br = (const float*)d_in[8];
    const float* bz = (const float*)d_in[9];
    const float* bh = (const float*)d_in[10];
    float* out = (float*)d_out;
    float* out_hnew = out;
    float* out_ht   = out + (size_t)1024 * HD;

    cudaFuncSetAttribute(gru_prep, cudaFuncAttributeMaxDynamicSharedMemorySize, 128 * 129 * 4);
    cudaFuncSetAttribute(gru_main, cudaFuncAttributeMaxDynamicSharedMemorySize, (int)SMEM_MAIN);

    gru_prep<<<dim3(256, 3), 256, 128 * 129 * 4>>>(Uz, Ur, Uh);
    gru_main<<<dim3(16, 256), 256, SMEM_MAIN>>>(X, h, Wr, Wz, Wh, br, bz, bh,
                                                out_hnew, out_ht);
}

// round 14
// speedup vs baseline: 1.4932x; 1.4932x over previous
#include <cuda_runtime.h>
#include <cuda_fp16.h>
#include <stdint.h>
#include <math.h>

constexpr int I_SZ = 256, D_SZ = 128, HD = 32768, MB = 64;
constexpr int ROWB = 272;                    // padded row: 136 halfs = 272 B
constexpr uint32_t A_PLANE = 64 * ROWB;      // 17408 B  [64][136] fp16
constexpr uint32_t U_PLANE = 128 * ROWB;     // 34816 B  [128][136] fp16
constexpr uint32_t SM_A  = 0;                // fp16 A plane (hg, later rh)
constexpr uint32_t SM_U  = A_PLANE;          // single U buffer (Uz -> Ur -> Uh)
constexpr uint32_t SM_WB = SM_U + U_PLANE;   // 52224; 6*128 floats
constexpr uint32_t SM_X  = SM_WB + 3072;     // 64 floats
constexpr uint32_t SMEM_MAIN = SM_X + 256;   // 55552 B -> 3 CTAs/SM

// U scratch: [gate z/r/h][group] -> 32KB fp16 [n=128][k=128]
__device__ __align__(256) unsigned char g_Uscr[3ull * 256 * 32768];

__device__ __forceinline__ uint32_t smem_u32(const void* p) {
    uint32_t a;
    asm("{ .reg .u64 t; cvta.to.shared.u64 t, %1; cvt.u32.u64 %0, t; }" : "=r"(a) : "l"(p));
    return a;
}
#define CP16(dst, src) asm volatile("cp.async.cg.shared.global [%0], [%1], 16;" :: "r"(dst), "l"(src))
#define CP_COMMIT()    asm volatile("cp.async.commit_group;" ::: "memory")
#define CP_WAIT(n)     asm volatile("cp.async.wait_group %0;" :: "n"(n) : "memory")
#define LDSM4(R, addr)                                                          \
    asm volatile("ldmatrix.sync.aligned.m8n8.x4.shared.b16 {%0,%1,%2,%3}, [%4];"\
        : "=r"((R)[0]), "=r"((R)[1]), "=r"((R)[2]), "=r"((R)[3]) : "r"(addr))
#define MMA16816(c, a0, a1, a2, a3, b0, b1)                                     \
    asm volatile("mma.sync.aligned.m16n8k16.row.col.f32.f16.f16.f32 "           \
        "{%0,%1,%2,%3}, {%4,%5,%6,%7}, {%8,%9}, {%0,%1,%2,%3};"                 \
        : "+f"((c)[0]), "+f"((c)[1]), "+f"((c)[2]), "+f"((c)[3])                \
        : "r"(a0), "r"(a1), "r"(a2), "r"(a3), "r"(b0), "r"(b1))

// HW tanh (MUFU.TANH): numerically verified free vs __expf path (R13 rel_err identical)
__device__ __forceinline__ float tanha(float x) {
    float y;
    asm("tanh.approx.f32 %0, %1;" : "=f"(y) : "f"(x));
    return y;
}
__device__ __forceinline__ float sigf(float x) {      // sigmoid = 0.5 + 0.5*tanh(x/2)
    return fmaf(tanha(0.5f * x), 0.5f, 0.5f);
}

// ---------- prep: U[i][k][n] -> B[n][k] fp16 plane ----------
__global__ __launch_bounds__(256) void gru_prep(const float* __restrict__ Uz,
                                                const float* __restrict__ Ur,
                                                const float* __restrict__ Uh) {
    extern __shared__ float sf[];  // [128][129]
    const int i = blockIdx.x, g = blockIdx.y, tid = threadIdx.x;
    const float* Ui = ((g == 0) ? Uz : (g == 1) ? Ur : Uh) + (size_t)i * D_SZ * D_SZ;
    for (int t = tid; t < D_SZ * D_SZ; t += 256) sf[(t >> 7) * 129 + (t & 127)] = Ui[t];
    __syncthreads();
    unsigned char* hp = g_Uscr + (size_t)(g * 256 + i) * 32768;
    for (int c = tid; c < 2048; c += 256) {
        int n = c >> 4, k0 = (c & 15) * 8;
        uint32_t hw[4];
#pragma unroll
        for (int j = 0; j < 4; j++) {
            __half h0 = __float2half_rn(sf[(k0 + 2 * j) * 129 + n]);      // B[n][k]=U[k][n]
            __half h1 = __float2half_rn(sf[(k0 + 2 * j + 1) * 129 + n]);
            hw[j] = (uint32_t)__half_as_ushort(h0) | ((uint32_t)__half_as_ushort(h1) << 16);
        }
        *(uint4*)(hp + n * 256 + k0 * 2) = make_uint4(hw[0], hw[1], hw[2], hw[3]);
    }
}

// cp.async one U gate (32KB) into the smem U buffer
__device__ __forceinline__ void cp_u(uint32_t dst, const unsigned char* src, int tid) {
#pragma unroll
    for (int t = tid; t < 2048; t += 256) {
        uint32_t row = t >> 4, c = t & 15;
        CP16(dst + row * ROWB + c * 16, src + (size_t)t * 16);
    }
    CP_COMMIT();
}

// GEMM: acc += A * U   (warp tile M=32, N=32, K=128; 64 MMAs)
__device__ __forceinline__ void gemm1(uint32_t sb, int warp_m, int warp_n,
                                      uint32_t offA, uint32_t offB, float acc[2][4][4]) {
#pragma unroll
    for (int mi = 0; mi < 2; mi++)
#pragma unroll
        for (int ni = 0; ni < 4; ni++)
#pragma unroll
            for (int q = 0; q < 4; q++) acc[mi][ni][q] = 0.0f;
#pragma unroll
    for (int ks = 0; ks < 8; ks++) {
        const uint32_t kb = ks * 32;
        uint32_t A[2][4], B[2][4];
#pragma unroll
        for (int mi = 0; mi < 2; mi++)
            LDSM4(A[mi], sb + SM_A + (warp_m + mi * 16) * ROWB + kb + offA);
#pragma unroll
        for (int nj = 0; nj < 2; nj++)
            LDSM4(B[nj], sb + SM_U + (warp_n + nj * 16) * ROWB + kb + offB);
#pragma unroll
        for (int mi = 0; mi < 2; mi++)
#pragma unroll
            for (int nj = 0; nj < 2; nj++)
#pragma unroll
                for (int hh = 0; hh < 2; hh++)
                    MMA16816(acc[mi][nj * 2 + hh],
                             A[mi][0], A[mi][1], A[mi][2], A[mi][3],
                             B[nj][hh * 2], B[nj][hh * 2 + 1]);
    }
}

// ---------- main: M=64/CTA, single U buffer, 3 CTAs/SM ----------
__global__ __launch_bounds__(256, 3) void gru_main(
    const float* __restrict__ X, const float* __restrict__ hs,
    const float* __restrict__ Wr, const float* __restrict__ Wz, const float* __restrict__ Wh,
    const float* __restrict__ br, const float* __restrict__ bz, const float* __restrict__ bh,
    float* __restrict__ out_hnew, float* __restrict__ out_ht) {
    extern __shared__ __align__(16) unsigned char smem[];
    const uint32_t sb = smem_u32(smem);
    const int tid = threadIdx.x, warp = tid >> 5, l = tid & 31;
    const int i = blockIdx.y, b0 = blockIdx.x * MB;

    float* wb  = (float*)(smem + SM_WB);  // wz|bz|wr|br|wh|bh
    float* x_s = (float*)(smem + SM_X);

    const unsigned char* uz = g_Uscr + (size_t)(0 * 256 + i) * 32768;
    const unsigned char* ur = g_Uscr + (size_t)(1 * 256 + i) * 32768;
    const unsigned char* uh = g_Uscr + (size_t)(2 * 256 + i) * 32768;
    cp_u(sb + SM_U, uz, tid);

    if (tid < 128) {
        wb[tid]       = Wz[i * D_SZ + tid];
        wb[128 + tid] = bz[i * D_SZ + tid];
        wb[256 + tid] = Wr[i * D_SZ + tid];
        wb[384 + tid] = br[i * D_SZ + tid];
        wb[512 + tid] = Wh[i * D_SZ + tid];
        wb[640 + tid] = bh[i * D_SZ + tid];
    }
    if (tid < MB) x_s[tid] = X[(size_t)(b0 + tid) * I_SZ + i];

    // A <= fp16(hg)
    for (int c = tid; c < 1024; c += 256) {
        int row = c >> 4, k0 = (c & 15) * 8;
        const float4* g = (const float4*)(hs + (size_t)(b0 + row) * HD + (size_t)i * D_SZ + k0);
        float4 v0 = g[0], v1 = g[1];
        float v[8] = {v0.x, v0.y, v0.z, v0.w, v1.x, v1.y, v1.z, v1.w};
        uint32_t hw[4];
#pragma unroll
        for (int j = 0; j < 4; j++) {
            __half h0 = __float2half_rn(v[2 * j]), h1 = __float2half_rn(v[2 * j + 1]);
            hw[j] = (uint32_t)__half_as_ushort(h0) | ((uint32_t)__half_as_ushort(h1) << 16);
        }
        *(uint4*)(smem + SM_A + row * ROWB + k0 * 2) = make_uint4(hw[0], hw[1], hw[2], hw[3]);
    }
    CP_WAIT(0);
    __syncthreads();             // [1] A + Uz resident

    const int warp_m = (warp & 1) * 32, warp_n = (warp >> 1) * 32;
    const uint32_t offA = (uint32_t)((l & 15) * ROWB + (l >> 4) * 16);
    const uint32_t offB = (uint32_t)((l & 7) * ROWB + ((l >> 4) & 1) * (8 * ROWB) +
                                     ((l >> 3) & 1) * 16);
    float acc[2][4][4];
    half2 z2[2][4][2];           // z gate packed fp16 (8 regs)

    // ---- z gate ----
    gemm1(sb, warp_m, warp_n, offA, offB, acc);
    __syncthreads();             // [2] Uz reads done
    cp_u(sb + SM_U, ur, tid);    // Ur -> U, overlaps z epilogue
#pragma unroll
    for (int mi = 0; mi < 2; mi++)
#pragma unroll
        for (int j = 0; j < 4; j++) {
            int col = warp_n + j * 8 + (l & 3) * 2;
            float w0 = wb[col], w1 = wb[col + 1], c0 = wb[128 + col], c1 = wb[129 + col];
#pragma unroll
            for (int rr = 0; rr < 2; rr++) {
                int row = warp_m + mi * 16 + rr * 8 + (l >> 2);
                float xv = x_s[row];
                float z0 = sigf(acc[mi][j][rr * 2] + xv * w0 + c0);
                float z1 = sigf(acc[mi][j][rr * 2 + 1] + xv * w1 + c1);
                z2[mi][j][rr] = __floats2half2_rn(z0, z1);
            }
        }
    CP_WAIT(0);
    __syncthreads();             // [3] Ur resident

    // ---- r gate ----
    gemm1(sb, warp_m, warp_n, offA, offB, acc);
    __syncthreads();             // [4] Ur + A reads done
    cp_u(sb + SM_U, uh, tid);    // Uh -> U, overlaps r epilogue
#pragma unroll
    for (int mi = 0; mi < 2; mi++)
#pragma unroll
        for (int j = 0; j < 4; j++) {
            int col = warp_n + j * 8 + (l & 3) * 2;
            float w0 = wb[256 + col], w1 = wb[257 + col];
            float c0 = wb[384 + col], c1 = wb[385 + col];
#pragma unroll
            for (int rr = 0; rr < 2; rr++) {
                int row = warp_m + mi * 16 + rr * 8 + (l >> 2);
                float xv = x_s[row];
                half2* pA = (half2*)(smem + SM_A + row * ROWB + col * 2);
                half2 hg2 = *pA;
                float r0 = sigf(acc[mi][j][rr * 2] + xv * w0 + c0);
                float r1 = sigf(acc[mi][j][rr * 2 + 1] + xv * w1 + c1);
                *pA = __halves2half2(
                    __float2half_rn(r0 * __half2float(__low2half(hg2))),
                    __float2half_rn(r1 * __half2float(__high2half(hg2))));
            }
        }
    CP_WAIT(0);
    __syncthreads();             // [5] Uh + rh plane ready

    // ---- h gate + fused combine (tail: global hg via __ldg, no barrier) ----
    gemm1(sb, warp_m, warp_n, offA, offB, acc);
#pragma unroll
    for (int mi = 0; mi < 2; mi++)
#pragma unroll
        for (int j = 0; j < 4; j++) {
            int col = warp_n + j * 8 + (l & 3) * 2;
            float w0 = wb[512 + col], w1 = wb[513 + col];
            float c0 = wb[640 + col], c1 = wb[641 + col];
#pragma unroll
            for (int rr = 0; rr < 2; rr++) {
                int row = warp_m + mi * 16 + rr * 8 + (l >> 2);
                float xv = x_s[row];
                size_t gidx = (size_t)(b0 + row) * HD + (size_t)i * D_SZ + col;
                float2 hg = __ldg((const float2*)(hs + gidx));
                float t0 = tanha(acc[mi][j][rr * 2] + xv * w0 + c0);
                float t1 = tanha(acc[mi][j][rr * 2 + 1] + xv * w1 + c1);
                float z0 = __half2float(__low2half(z2[mi][j][rr]));
                float z1 = __half2float(__high2half(z2[mi][j][rr]));
                *(float2*)(out_ht + gidx)   = make_float2(t0, t1);
                *(float2*)(out_hnew + gidx) = make_float2(z0 * hg.x + (1.0f - z0) * t0,
                                                          z1 * hg.y + (1.0f - z1) * t1);
            }
        }
}

extern "C" void kernel_launch(void* const* d_in, const int* in_sizes, int n_in,
                              void* d_out, int out_size) {
    const float* X  = (const float*)d_in[0];
    const float* h  = (const float*)d_in[1];
    const float* Wr = (const float*)d_in[2];
    const float* Wz = (const float*)d_in[3];
    const float* Wh = (const float*)d_in[4];
    const float* Ur = (const float*)d_in[5];
    const float* Uz = (const float*)d_in[6];
    const float* Uh = (const float*)d_in[7];
    const float* br = (const float*)d_in[8];
    const float* bz = (const float*)d_in[9];
    const float* bh = (const float*)d_in[10];
    float* out = (float*)d_out;
    float* out_hnew = out;
    float* out_ht   = out + (size_t)1024 * HD;

    cudaFuncSetAttribute(gru_prep, cudaFuncAttributeMaxDynamicSharedMemorySize, 128 * 129 * 4);
    cudaFuncSetAttribute(gru_main, cudaFuncAttributeMaxDynamicSharedMemorySize, (int)SMEM_MAIN);

    gru_prep<<<dim3(256, 3), 256, 128 * 129 * 4>>>(Uz, Ur, Uh);
    gru_main<<<dim3(16, 256), 256, SMEM_MAIN>>>(X, h, Wr, Wz, Wh, br, bz, bh,
                                                out_hnew, out_ht);
}

// round 15
// speedup vs baseline: 1.5526x; 1.0398x over previous
#include <cuda_runtime.h>
#include <cuda_fp16.h>
#include <stdint.h>
#include <math.h>

constexpr int I_SZ = 256, D_SZ = 128, HD = 32768, MB = 64;
constexpr int ROWB  = 272;                   // full U/A row: 136 halfs = 272 B
constexpr int ROWBX = 144;                   // half-plane row: 64 halfs + 16B pad
constexpr uint32_t A_PLANE = 64 * ROWB;      // 17408 B  [64][136] fp16
constexpr uint32_t U_PLANE = 128 * ROWB;     // 34816 B  [128][136] fp16
constexpr uint32_t X_PLANE = 128 * ROWBX;    // 18432 B  [128][72] fp16 (k-half)
constexpr uint32_t SM_A  = 0;                // fp16 A plane (hg, later rh)
constexpr uint32_t SM_U  = A_PLANE;          // main U buffer
constexpr uint32_t SM_XH = SM_U + U_PLANE;   // 52224: k-half0 staging plane
constexpr uint32_t SM_WB = SM_XH + X_PLANE;  // 70656; 6*128 floats
constexpr uint32_t SM_XS = SM_WB + 3072;     // 64 floats
constexpr uint32_t SMEM_MAIN = SM_XS + 256;  // 73984 B -> 3 CTAs/SM (217 KB)

// U scratch: [gate z/r/h][group] -> 32KB fp16 [n=128][k=128] (256B rows)
__device__ __align__(256) unsigned char g_Uscr[3ull * 256 * 32768];

__device__ __forceinline__ uint32_t smem_u32(const void* p) {
    uint32_t a;
    asm("{ .reg .u64 t; cvta.to.shared.u64 t, %1; cvt.u32.u64 %0, t; }" : "=r"(a) : "l"(p));
    return a;
}
#define CP16(dst, src) asm volatile("cp.async.cg.shared.global [%0], [%1], 16;" :: "r"(dst), "l"(src))
#define CP_COMMIT()    asm volatile("cp.async.commit_group;" ::: "memory")
#define CP_WAIT(n)     asm volatile("cp.async.wait_group %0;" :: "n"(n) : "memory")
#define LDSM4(R, addr)                                                          \
    asm volatile("ldmatrix.sync.aligned.m8n8.x4.shared.b16 {%0,%1,%2,%3}, [%4];"\
        : "=r"((R)[0]), "=r"((R)[1]), "=r"((R)[2]), "=r"((R)[3]) : "r"(addr))
#define MMA16816(c, a0, a1, a2, a3, b0, b1)                                     \
    asm volatile("mma.sync.aligned.m16n8k16.row.col.f32.f16.f16.f32 "           \
        "{%0,%1,%2,%3}, {%4,%5,%6,%7}, {%8,%9}, {%0,%1,%2,%3};"                 \
        : "+f"((c)[0]), "+f"((c)[1]), "+f"((c)[2]), "+f"((c)[3])                \
        : "r"(a0), "r"(a1), "r"(a2), "r"(a3), "r"(b0), "r"(b1))

__device__ __forceinline__ float tanha(float x) {
    float y;
    asm("tanh.approx.f32 %0, %1;" : "=f"(y) : "f"(x));
    return y;
}
__device__ __forceinline__ float sigf(float x) {      // sigmoid = 0.5 + 0.5*tanh(x/2)
    return fmaf(tanha(0.5f * x), 0.5f, 0.5f);
}

// ---------- prep: U[i][k][n] -> B[n][k] fp16 plane (vectorized fill) ----------
__global__ __launch_bounds__(256) void gru_prep(const float* __restrict__ Uz,
                                                const float* __restrict__ Ur,
                                                const float* __restrict__ Uh) {
    extern __shared__ float sf[];  // [128][129]
    const int i = blockIdx.x, g = blockIdx.y, tid = threadIdx.x;
    const float* Ui = ((g == 0) ? Uz : (g == 1) ? Ur : Uh) + (size_t)i * D_SZ * D_SZ;
    const float4* u4 = (const float4*)Ui;
#pragma unroll 4
    for (int t = tid; t < 4096; t += 256) {        // 16384 floats / 4
        int row = t >> 5, c4 = (t & 31) * 4;
        float4 v = u4[t];
        float* dst = sf + row * 129 + c4;
        dst[0] = v.x; dst[1] = v.y; dst[2] = v.z; dst[3] = v.w;
    }
    __syncthreads();
    unsigned char* hp = g_Uscr + (size_t)(g * 256 + i) * 32768;
    for (int c = tid; c < 2048; c += 256) {
        int n = c >> 4, k0 = (c & 15) * 8;
        uint32_t hw[4];
#pragma unroll
        for (int j = 0; j < 4; j++) {
            __half h0 = __float2half_rn(sf[(k0 + 2 * j) * 129 + n]);      // B[n][k]=U[k][n]
            __half h1 = __float2half_rn(sf[(k0 + 2 * j + 1) * 129 + n]);
            hw[j] = (uint32_t)__half_as_ushort(h0) | ((uint32_t)__half_as_ushort(h1) << 16);
        }
        *(uint4*)(hp + n * 256 + k0 * 2) = make_uint4(hw[0], hw[1], hw[2], hw[3]);
    }
}

// cp.async full U gate (32KB) into the main smem U buffer
__device__ __forceinline__ void cp_u(uint32_t dst, const unsigned char* src, int tid) {
#pragma unroll
    for (int t = tid; t < 2048; t += 256) {
        uint32_t row = t >> 4, c = t & 15;
        CP16(dst + row * ROWB + c * 16, src + (size_t)t * 16);
    }
    CP_COMMIT();
}
// k-half0 (bytes [0,128) of each row) -> X plane (ROWBX rows)
__device__ __forceinline__ void cp_uh0(uint32_t xdst, const unsigned char* src, int tid) {
#pragma unroll
    for (int t = tid; t < 1024; t += 256) {
        uint32_t row = t >> 3, c = t & 7;
        CP16(xdst + row * ROWBX + c * 16, src + row * 256 + c * 16);
    }
    CP_COMMIT();
}
// k-half1 (bytes [128,256) of each row) -> main buffer rows at byte offset 128
__device__ __forceinline__ void cp_uh1(uint32_t udst, const unsigned char* src, int tid) {
#pragma unroll
    for (int t = tid; t < 1024; t += 256) {
        uint32_t row = t >> 3, c = t & 7;
        CP16(udst + row * ROWB + 128 + c * 16, src + row * 256 + 128 + c * 16);
    }
    CP_COMMIT();
}

// GEMM from a single full plane (z gate): warp tile M32 x N32, K=128
__device__ __forceinline__ void gemm_full(uint32_t sb, int warp_m, int warp_n,
                                          uint32_t offA, uint32_t offB, float acc[2][4][4]) {
#pragma unroll
    for (int mi = 0; mi < 2; mi++)
#pragma unroll
        for (int ni = 0; ni < 4; ni++)
#pragma unroll
            for (int q = 0; q < 4; q++) acc[mi][ni][q] = 0.0f;
#pragma unroll
    for (int ks = 0; ks < 8; ks++) {
        const uint32_t kb = ks * 32;
        uint32_t A[2][4], B[2][4];
#pragma unroll
        for (int mi = 0; mi < 2; mi++)
            LDSM4(A[mi], sb + SM_A + (warp_m + mi * 16) * ROWB + kb + offA);
#pragma unroll
        for (int nj = 0; nj < 2; nj++)
            LDSM4(B[nj], sb + SM_U + (warp_n + nj * 16) * ROWB + kb + offB);
#pragma unroll
        for (int mi = 0; mi < 2; mi++)
#pragma unroll
            for (int nj = 0; nj < 2; nj++)
#pragma unroll
                for (int hh = 0; hh < 2; hh++)
                    MMA16816(acc[mi][nj * 2 + hh],
                             A[mi][0], A[mi][1], A[mi][2], A[mi][3],
                             B[nj][hh * 2], B[nj][hh * 2 + 1]);
    }
}

// GEMM split across X (ks 0-3) and main buffer (ks 4-7)  (r and h gates)
__device__ __forceinline__ void gemm_split(uint32_t sb, int warp_m, int warp_n,
                                           uint32_t offA, uint32_t offB, uint32_t offBX,
                                           float acc[2][4][4]) {
#pragma unroll
    for (int mi = 0; mi < 2; mi++)
#pragma unroll
        for (int ni = 0; ni < 4; ni++)
#pragma unroll
            for (int q = 0; q < 4; q++) acc[mi][ni][q] = 0.0f;
#pragma unroll
    for (int ks = 0; ks < 8; ks++) {
        const uint32_t kb = ks * 32;
        uint32_t A[2][4], B[2][4];
#pragma unroll
        for (int mi = 0; mi < 2; mi++)
            LDSM4(A[mi], sb + SM_A + (warp_m + mi * 16) * ROWB + kb + offA);
        if (ks < 4) {
#pragma unroll
            for (int nj = 0; nj < 2; nj++)
                LDSM4(B[nj], sb + SM_XH + (warp_n + nj * 16) * ROWBX + kb + offBX);
        } else {
#pragma unroll
            for (int nj = 0; nj < 2; nj++)
                LDSM4(B[nj], sb + SM_U + (warp_n + nj * 16) * ROWB + kb + offB);
        }
#pragma unroll
        for (int mi = 0; mi < 2; mi++)
#pragma unroll
            for (int nj = 0; nj < 2; nj++)
#pragma unroll
                for (int hh = 0; hh < 2; hh++)
                    MMA16816(acc[mi][nj * 2 + hh],
                             A[mi][0], A[mi][1], A[mi][2], A[mi][3],
                             B[nj][hh * 2], B[nj][hh * 2 + 1]);
    }
}

// ---------- main: M=64/CTA, 1.5-buffer U pipeline, 3 CTAs/SM ----------
__global__ __launch_bounds__(256, 3) void gru_main(
    const float* __restrict__ X, const float* __restrict__ hs,
    const float* __restrict__ Wr, const float* __restrict__ Wz, const float* __restrict__ Wh,
    const float* __restrict__ br, const float* __restrict__ bz, const float* __restrict__ bh,
    float* __restrict__ out_hnew, float* __restrict__ out_ht) {
    extern __shared__ __align__(16) unsigned char smem[];
    const uint32_t sb = smem_u32(smem);
    const int tid = threadIdx.x, warp = tid >> 5, l = tid & 31;
    const int i = blockIdx.y, b0 = blockIdx.x * MB;

    float* wb  = (float*)(smem + SM_WB);  // wz|bz|wr|br|wh|bh
    float* x_s = (float*)(smem + SM_XS);

    const unsigned char* uz = g_Uscr + (size_t)(0 * 256 + i) * 32768;
    const unsigned char* ur = g_Uscr + (size_t)(1 * 256 + i) * 32768;
    const unsigned char* uh = g_Uscr + (size_t)(2 * 256 + i) * 32768;
    cp_u(sb + SM_U, uz, tid);     // group 1: Uz (full)
    cp_uh0(sb + SM_XH, ur, tid);  // group 2: Ur k-half0 (hidden under A-fill + z gemm)

    if (tid < 128) {
        wb[tid]       = Wz[i * D_SZ + tid];
        wb[128 + tid] = bz[i * D_SZ + tid];
        wb[256 + tid] = Wr[i * D_SZ + tid];
        wb[384 + tid] = br[i * D_SZ + tid];
        wb[512 + tid] = Wh[i * D_SZ + tid];
        wb[640 + tid] = bh[i * D_SZ + tid];
    }
    if (tid < MB) x_s[tid] = X[(size_t)(b0 + tid) * I_SZ + i];

    // A <= fp16(hg)
    for (int c = tid; c < 1024; c += 256) {
        int row = c >> 4, k0 = (c & 15) * 8;
        const float4* g = (const float4*)(hs + (size_t)(b0 + row) * HD + (size_t)i * D_SZ + k0);
        float4 v0 = g[0], v1 = g[1];
        float v[8] = {v0.x, v0.y, v0.z, v0.w, v1.x, v1.y, v1.z, v1.w};
        uint32_t hw[4];
#pragma unroll
        for (int j = 0; j < 4; j++) {
            __half h0 = __float2half_rn(v[2 * j]), h1 = __float2half_rn(v[2 * j + 1]);
            hw[j] = (uint32_t)__half_as_ushort(h0) | ((uint32_t)__half_as_ushort(h1) << 16);
        }
        *(uint4*)(smem + SM_A + row * ROWB + k0 * 2) = make_uint4(hw[0], hw[1], hw[2], hw[3]);
    }
    CP_WAIT(1);                  // Uz resident (Ur.h0 may be in flight)
    __syncthreads();             // [1]

    const int warp_m = (warp & 1) * 32, warp_n = (warp >> 1) * 32;
    const uint32_t offA  = (uint32_t)((l & 15) * ROWB + (l >> 4) * 16);
    const uint32_t offB  = (uint32_t)((l & 7) * ROWB + ((l >> 4) & 1) * (8 * ROWB) +
                                      ((l >> 3) & 1) * 16);
    const uint32_t offBX = (uint32_t)((l & 7) * ROWBX + ((l >> 4) & 1) * (8 * ROWBX) +
                                      ((l >> 3) & 1) * 16);
    float acc[2][4][4];
    half2 z2[2][4][2];           // z gate packed fp16 (8 regs)

    // ---- z gate ----
    gemm_full(sb, warp_m, warp_n, offA, offB, acc);
    __syncthreads();             // [2] Uz reads done
    cp_uh1(sb + SM_U, ur, tid);  // only 16KB left to load; overlaps z epilogue
#pragma unroll
    for (int mi = 0; mi < 2; mi++)
#pragma unroll
        for (int j = 0; j < 4; j++) {
            int col = warp_n + j * 8 + (l & 3) * 2;
            float w0 = wb[col], w1 = wb[col + 1], c0 = wb[128 + col], c1 = wb[129 + col];
#pragma unroll
            for (int rr = 0; rr < 2; rr++) {
                int row = warp_m + mi * 16 + rr * 8 + (l >> 2);
                float xv = x_s[row];
                float z0 = sigf(acc[mi][j][rr * 2] + xv * w0 + c0);
                float z1 = sigf(acc[mi][j][rr * 2 + 1] + xv * w1 + c1);
                z2[mi][j][rr] = __floats2half2_rn(z0, z1);
            }
        }
    CP_WAIT(0);
    __syncthreads();             // [3] Ur halves resident

    // ---- r gate ----
    gemm_split(sb, warp_m, warp_n, offA, offB, offBX, acc);
    __syncthreads();             // [4] Ur + A reads done
    cp_uh0(sb + SM_XH, uh, tid); // Uh both halves; overlap r epilogue
    cp_uh1(sb + SM_U, uh, tid);
#pragma unroll
    for (int mi = 0; mi < 2; mi++)
#pragma unroll
        for (int j = 0; j < 4; j++) {
            int col = warp_n + j * 8 + (l & 3) * 2;
            float w0 = wb[256 + col], w1 = wb[257 + col];
            float c0 = wb[384 + col], c1 = wb[385 + col];
#pragma unroll
            for (int rr = 0; rr < 2; rr++) {
                int row = warp_m + mi * 16 + rr * 8 + (l >> 2);
                float xv = x_s[row];
                half2* pA = (half2*)(smem + SM_A + row * ROWB + col * 2);
                half2 hg2 = *pA;
                float r0 = sigf(acc[mi][j][rr * 2] + xv * w0 + c0);
                float r1 = sigf(acc[mi][j][rr * 2 + 1] + xv * w1 + c1);
                *pA = __halves2half2(
                    __float2half_rn(r0 * __half2float(__low2half(hg2))),
                    __float2half_rn(r1 * __half2float(__high2half(hg2))));
            }
        }
    CP_WAIT(0);
    __syncthreads();             // [5] Uh + rh plane ready

    // ---- h gate + fused combine (tail: global hg via __ldg, no barrier) ----
    gemm_split(sb, warp_m, warp_n, offA, offB, offBX, acc);
#pragma unroll
    for (int mi = 0; mi < 2; mi++)
#pragma unroll
        for (int j = 0; j < 4; j++) {
            int col = warp_n + j * 8 + (l & 3) * 2;
            float w0 = wb[512 + col], w1 = wb[513 + col];
            float c0 = wb[640 + col], c1 = wb[641 + col];
#pragma unroll
            for (int rr = 0; rr < 2; rr++) {
                int row = warp_m + mi * 16 + rr * 8 + (l >> 2);
                float xv = x_s[row];
                size_t gidx = (size_t)(b0 + row) * HD + (size_t)i * D_SZ + col;
                float2 hg = __ldg((const float2*)(hs + gidx));
                float t0 = tanha(acc[mi][j][rr * 2] + xv * w0 + c0);
                float t1 = tanha(acc[mi][j][rr * 2 + 1] + xv * w1 + c1);
                float z0 = __half2float(__low2half(z2[mi][j][rr]));
                float z1 = __half2float(__high2half(z2[mi][j][rr]));
                *(float2*)(out_ht + gidx)   = make_float2(t0, t1);
                *(float2*)(out_hnew + gidx) = make_float2(z0 * hg.x + (1.0f - z0) * t0,
                                                          z1 * hg.y + (1.0f - z1) * t1);
            }
        }
}

extern "C" void kernel_launch(void* const* d_in, const int* in_sizes, int n_in,
                              void* d_out, int out_size) {
    const float* X  = (const float*)d_in[0];
    const float* h  = (const float*)d_in[1];
    const float* Wr = (const float*)d_in[2];
    const float* Wz = (const float*)d_in[3];
    const float* Wh = (const float*)d_in[4];
    const float* Ur = (const float*)d_in[5];
    const float* Uz = (const float*)d_in[6];
    const float* Uh = (const float*)d_in[7];
    const float* br = (const float*)d_in[8];
    const float* bz = (const float*)d_in[9];
    const float* bh = (const float*)d_in[10];
    float* out = (float*)d_out;
    float* out_hnew = out;
    float* out_ht   = out + (size_t)1024 * HD;

    cudaFuncSetAttribute(gru_prep, cudaFuncAttributeMaxDynamicSharedMemorySize, 128 * 129 * 4);
    cudaFuncSetAttribute(gru_main, cudaFuncAttributeMaxDynamicSharedMemorySize, (int)SMEM_MAIN);

    gru_prep<<<dim3(256, 3), 256, 128 * 129 * 4>>>(Uz, Ur, Uh);
    gru_main<<<dim3(16, 256), 256, SMEM_MAIN>>>(X, h, Wr, Wz, Wh, br, bz, bh,
                                                out_hnew, out_ht);
}